// round 3
// baseline (speedup 1.0000x reference)
#include <cuda_runtime.h>
#include <cuda_bf16.h>

// Mixed pooling, 2x2 stride-2, NHWC:
//   out[b,ho,wo,c] = (1-k)*max(window) + k*mean(window)
// x: [32,256,256,128] f32, k: [32,128,128,128] i32, out: [32,128,128,128] f32
//
// HBM-bound streaming kernel, traffic already minimal (1.5 GiB).
// R3: 2 ADJACENT float4 groups per thread (32B contiguous per tap),
// default cache policy (best DRAM% in R1), MLP=10.

#define B_  32
#define H_  256
#define W_  256
#define C_  128
#define HO_ (H_ / 2)
#define WO_ (W_ / 2)
#define C4_ (C_ / 4)                    // 32 float4 per pixel
#define ROW4_ (W_ * C_ / 4)             // 8192 float4 per input row
#define TOTAL4_ (B_ * HO_ * WO_ * C4_)  // 16,777,216
#define NTHREADS_TOTAL (TOTAL4_ / 2)    // each thread: 2 adjacent groups

__device__ __forceinline__ float4 blend4(float4 p00, float4 p01,
                                         float4 p10, float4 p11, int4 kv)
{
    float4 r;
    {
        float mx = fmaxf(fmaxf(p00.x, p01.x), fmaxf(p10.x, p11.x));
        float mn = (p00.x + p01.x + p10.x + p11.x) * 0.25f;
        r.x = fmaf((float)kv.x, mn - mx, mx);
    }
    {
        float mx = fmaxf(fmaxf(p00.y, p01.y), fmaxf(p10.y, p11.y));
        float mn = (p00.y + p01.y + p10.y + p11.y) * 0.25f;
        r.y = fmaf((float)kv.y, mn - mx, mx);
    }
    {
        float mx = fmaxf(fmaxf(p00.z, p01.z), fmaxf(p10.z, p11.z));
        float mn = (p00.z + p01.z + p10.z + p11.z) * 0.25f;
        r.z = fmaf((float)kv.z, mn - mx, mx);
    }
    {
        float mx = fmaxf(fmaxf(p00.w, p01.w), fmaxf(p10.w, p11.w));
        float mn = (p00.w + p01.w + p10.w + p11.w) * 0.25f;
        r.w = fmaf((float)kv.w, mn - mx, mx);
    }
    return r;
}

__global__ __launch_bounds__(256) void mixed_pool_kernel(
    const float4* __restrict__ x,
    const int4*   __restrict__ k,
    float4*       __restrict__ out)
{
    int tid = blockIdx.x * blockDim.x + threadIdx.x;   // [0, TOTAL4_/2)
    int idx = tid * 2;                                  // first of 2 adjacent groups

    // idx -> (b, ho, wo, c4); C4_=32 (5b), WO_=128 (7b)
    // idx is even, both groups share wo/bho only if c4 < 31; since idx even and
    // 2 groups stay within the same pixel iff (idx & 31) != 31 — idx even means
    // c4 even, so c4 and c4+1 are always within the same 32-group pixel. Good.
    int c4  = idx & (C4_ - 1);
    int wo  = (idx >> 5) & (WO_ - 1);
    int bho = idx >> 12;                // b*HO_ + ho
    int base = (bho * 2 * W_ + 2 * wo) * C4_ + c4;

    float4 a00 = x[base];
    float4 b00 = x[base + 1];
    float4 a01 = x[base + C4_];
    float4 b01 = x[base + C4_ + 1];
    float4 a10 = x[base + ROW4_];
    float4 b10 = x[base + ROW4_ + 1];
    float4 a11 = x[base + ROW4_ + C4_];
    float4 b11 = x[base + ROW4_ + C4_ + 1];
    int4   ka  = k[idx];
    int4   kb  = k[idx + 1];

    out[idx]     = blend4(a00, a01, a10, a11, ka);
    out[idx + 1] = blend4(b00, b01, b10, b11, kb);
}

extern "C" void kernel_launch(void* const* d_in, const int* in_sizes, int n_in,
                              void* d_out, int out_size)
{
    const float4* x = (const float4*)d_in[0];
    const int4*   k = (const int4*)d_in[1];
    float4*       o = (float4*)d_out;

    const int threads = 256;
    const int blocks  = NTHREADS_TOTAL / threads;   // 32768
    mixed_pool_kernel<<<blocks, threads>>>(x, k, o);
}

// round 4
// speedup vs baseline: 1.0167x; 1.0167x over previous
#include <cuda_runtime.h>
#include <cuda_bf16.h>

// Mixed pooling, 2x2 stride-2, NHWC:
//   out[b,ho,wo,c] = (1-k)*max(window) + k*mean(window)
// x: [32,256,256,128] f32, k: [32,128,128,128] i32, out: [32,128,128,128] f32
//
// HBM-bound streaming kernel at ~91% of spec HBM; traffic is minimal.
// R4 = R1 layout (1 float4 group/thread, default cache policy — best measured)
// with 512-thread blocks to shave wave-transition/tail overhead.

#define B_  32
#define H_  256
#define W_  256
#define C_  128
#define HO_ (H_ / 2)
#define WO_ (W_ / 2)
#define C4_ (C_ / 4)                    // 32 float4 per pixel
#define ROW4_ (W_ * C_ / 4)             // 8192 float4 per input row
#define TOTAL4_ (B_ * HO_ * WO_ * C4_)  // 16,777,216

__global__ __launch_bounds__(512) void mixed_pool_kernel(
    const float4* __restrict__ x,
    const int4*   __restrict__ k,
    float4*       __restrict__ out)
{
    int idx = blockIdx.x * blockDim.x + threadIdx.x;

    // idx -> (b, ho, wo, c4); C4_=32 (5 bits), WO_=128 (7 bits), HO_=128 (7 bits)
    int c4  = idx & (C4_ - 1);
    int wo  = (idx >> 5) & (WO_ - 1);
    int bho = idx >> 12;                 // b*HO_ + ho

    // input base in float4 units: ((bho*2)*W + 2*wo)*C4 + c4
    int base = (bho * 2 * W_ + 2 * wo) * C4_ + c4;

    float4 p00 = x[base];
    float4 p01 = x[base + C4_];          // next column (wo*2+1)
    float4 p10 = x[base + ROW4_];        // next row (ho*2+1)
    float4 p11 = x[base + ROW4_ + C4_];
    int4   kv  = k[idx];

    float4 r;
    {
        float mx = fmaxf(fmaxf(p00.x, p01.x), fmaxf(p10.x, p11.x));
        float mn = (p00.x + p01.x + p10.x + p11.x) * 0.25f;
        r.x = fmaf((float)kv.x, mn - mx, mx);
    }
    {
        float mx = fmaxf(fmaxf(p00.y, p01.y), fmaxf(p10.y, p11.y));
        float mn = (p00.y + p01.y + p10.y + p11.y) * 0.25f;
        r.y = fmaf((float)kv.y, mn - mx, mx);
    }
    {
        float mx = fmaxf(fmaxf(p00.z, p01.z), fmaxf(p10.z, p11.z));
        float mn = (p00.z + p01.z + p10.z + p11.z) * 0.25f;
        r.z = fmaf((float)kv.z, mn - mx, mx);
    }
    {
        float mx = fmaxf(fmaxf(p00.w, p01.w), fmaxf(p10.w, p11.w));
        float mn = (p00.w + p01.w + p10.w + p11.w) * 0.25f;
        r.w = fmaf((float)kv.w, mn - mx, mx);
    }

    out[idx] = r;
}

extern "C" void kernel_launch(void* const* d_in, const int* in_sizes, int n_in,
                              void* d_out, int out_size)
{
    const float4* x = (const float4*)d_in[0];
    const int4*   k = (const int4*)d_in[1];
    float4*       o = (float4*)d_out;

    const int threads = 512;
    const int blocks  = TOTAL4_ / threads;   // 32768
    mixed_pool_kernel<<<blocks, threads>>>(x, k, o);
}